// round 17
// baseline (speedup 1.0000x reference)
#include <cuda_runtime.h>
#include <math.h>

#define B_DIM      256
#define B_UINT     64                // 64 uints (4 int8 batches each) per A_T row = 256 B
#define NB_DIM     50000
#define N_CYC      20000
#define P2_THREADS 64                // thread = one uint lane (4 batches)
#define P2_BASE    32                // entries owned per phase-2 block
#define P2_EXT     128               // staged entries (32 + 96 slack)
#define BATCH      8                 // gathers kept in flight per warp

// A_T[i] = 256 batch angles quantized to int8 (scale 127/pi); row = 64 uints.
__device__ unsigned g_ATq[(size_t)NB_DIM * B_UINT];    // 12.8 MB
__device__ double   g_accum;
__device__ unsigned g_done;

// ---------------------------------------------------------------------------
// Branchless fast atan2 (minimax, |err| < 1e-5 rad; subdominant to int8
// quantization).
// ---------------------------------------------------------------------------
__device__ __forceinline__ float fast_atan2f(float y, float x) {
    const float ax = fabsf(x), ay = fabsf(y);
    const float mx = fmaxf(ax, ay), mn = fminf(ax, ay);
    const float t = __fdividef(mn, mx);
    const float a = t * t;
    float r = fmaf(a, 0.0208351f, -0.0851330f);
    r = fmaf(r, a, 0.1801410f);
    r = fmaf(r, a, -0.3302995f);
    r = fmaf(r, a, 0.9998660f);
    r = r * t;
    if (ay > ax)  r = 1.57079632679f - r;
    if (x < 0.0f) r = 3.14159265359f - r;
    return copysignf(r, y);
}

// Quantize 4 consecutive-batch angles to packed int8x4 (scale 127/pi).
__device__ __forceinline__ unsigned pack4_q(float a0, float a1, float a2, float a3) {
    const float sc = 40.42535554534142f;   // 127/pi
    const int v0 = __float2int_rn(a0 * sc) & 0xFF;
    const int v1 = __float2int_rn(a1 * sc) & 0xFF;
    const int v2 = __float2int_rn(a2 * sc) & 0xFF;
    const int v3 = __float2int_rn(a3 * sc) & 0xFF;
    return (unsigned)(v0 | (v1 << 8) | (v2 << 16) | (v3 << 24));
}

// ---------------------------------------------------------------------------
// Phase 1: A_T[i][b] = q(atan2(s[b,i], c[b,i])).
// Tile 64 i x 64 b, block (16,16): thread = i-quad x batch-quad
// (8x LDG.128 front-batched, 16 atan2, 4 packed uints). c/s streaming
// (__ldcs). Transpose via smem; coalesced writes.
// ---------------------------------------------------------------------------
__global__ void phase1_atan2_transpose(const float* __restrict__ c,
                                       const float* __restrict__ s) {
    __shared__ unsigned tile[64][17];    // [i_local][b_quad]

    const int tx = threadIdx.x;          // 0..15 : i-quad
    const int ty = threadIdx.y;          // 0..15 : b-quad
    const int i_base = blockIdx.x * 64;
    const int b_base = blockIdx.y * 64;
    const int i0 = i_base + tx * 4;

    if (i0 < NB_DIM) {                   // i0%4==0, NB_DIM%4==0 -> safe float4
        const int b0 = b_base + 4 * ty;

        const float4* cp = (const float4*)(c + i0);
        const float4* sp = (const float4*)(s + i0);
        const size_t q = (size_t)NB_DIM / 4;

        const float4 c0 = __ldcs(cp + (size_t)(b0 + 0) * q);
        const float4 s0 = __ldcs(sp + (size_t)(b0 + 0) * q);
        const float4 c1 = __ldcs(cp + (size_t)(b0 + 1) * q);
        const float4 s1 = __ldcs(sp + (size_t)(b0 + 1) * q);
        const float4 c2 = __ldcs(cp + (size_t)(b0 + 2) * q);
        const float4 s2 = __ldcs(sp + (size_t)(b0 + 2) * q);
        const float4 c3 = __ldcs(cp + (size_t)(b0 + 3) * q);
        const float4 s3 = __ldcs(sp + (size_t)(b0 + 3) * q);

        tile[tx*4+0][ty] = pack4_q(fast_atan2f(s0.x, c0.x), fast_atan2f(s1.x, c1.x),
                                   fast_atan2f(s2.x, c2.x), fast_atan2f(s3.x, c3.x));
        tile[tx*4+1][ty] = pack4_q(fast_atan2f(s0.y, c0.y), fast_atan2f(s1.y, c1.y),
                                   fast_atan2f(s2.y, c2.y), fast_atan2f(s3.y, c3.y));
        tile[tx*4+2][ty] = pack4_q(fast_atan2f(s0.z, c0.z), fast_atan2f(s1.z, c1.z),
                                   fast_atan2f(s2.z, c2.z), fast_atan2f(s3.z, c3.z));
        tile[tx*4+3][ty] = pack4_q(fast_atan2f(s0.w, c0.w), fast_atan2f(s1.w, c1.w),
                                   fast_atan2f(s2.w, c2.w), fast_atan2f(s3.w, c3.w));
    }
    __syncthreads();

    // Write-out: 64 rows x 16 uints (64 B/row). 8 warps; per iteration a warp
    // covers 2 rows (lanes 0-15 -> row +0, lanes 16-31 -> row +1).
    const int tid  = ty * 16 + tx;
    const int w    = tid >> 5;
    const int lane = tid & 31;
    const int cc   = lane & 15;
    const int rsel = lane >> 4;
    #pragma unroll
    for (int k = 0; k < 4; ++k) {
        const int r  = w * 8 + k * 2 + rsel;
        const int gi = i_base + r;
        if (gi < NB_DIM)
            g_ATq[(size_t)gi * B_UINT + (b_base >> 2) + cc] = tile[r][cc];
    }

    if (blockIdx.x == 0 && blockIdx.y == 0 && tid == 0) {
        g_accum = 0.0;
        g_done = 0u;
    }
}

// ---------------------------------------------------------------------------
// Phase 2: 32 entries owned per block, 64 threads, thread = one uint lane
// (4 int8 batches). Meta: idx*64 | sign<<30 | rowchange<<31.
// Inner loop in BATCH=8 chunks: 8 independent LDG.32 issued, then scalar
// consumption: (signed char) extraction, +/-1 integer multiply for sign,
// 4 plain int accumulators, exact |.| flush at row changes.
// Last block writes the final scalar AND self-cleans the accumulators.
// ---------------------------------------------------------------------------
__global__ __launch_bounds__(P2_THREADS) void phase2_cycle_sum(
    const float* __restrict__ cysigns,
    const int*   __restrict__ cyinds,
    const int*   __restrict__ cyrows,
    float*       __restrict__ out,
    int E) {

    __shared__ unsigned sh[P2_EXT];
    __shared__ int      sh_se[2];
    __shared__ float    warp_sums[2];

    const int tid  = threadIdx.x;
    const int base = blockIdx.x * P2_BASE;
    const int n    = min(P2_EXT, E - base);

    // Stage meta.
    for (int j = tid; j < n; j += P2_THREADS) {
        const int e = base + j;
        const int idx = __ldg(&cyinds[e]);
        const unsigned sbit = __float_as_uint(__ldg(&cysigns[e])) >> 31;
        const int row  = __ldg(&cyrows[e]);
        const int prev = (e > 0) ? __ldg(&cyrows[e - 1]) : -1;
        const unsigned flag = (row != prev) ? 0x80000000u : 0u;
        sh[j] = (unsigned)(idx * B_UINT) | (sbit << 30) | flag;
    }
    __syncthreads();

    if (tid == 0) {
        int st = 0;
        while (st < n && !(sh[st] & 0x80000000u)) ++st;
        int en = (P2_BASE < n) ? P2_BASE : n;
        while (en < n && !(sh[en] & 0x80000000u)) ++en;
        sh_se[0] = st;
        sh_se[1] = en;
    }
    __syncthreads();
    const int st = sh_se[0];
    const int en = sh_se[1];

    int a0 = 0, a1 = 0, a2 = 0, a3 = 0;   // exact int accumulators
    float sum = 0.0f;

    for (int j0 = st; j0 < en; j0 += BATCH) {
        const int cnt = min(BATCH, en - j0);

        // Pass A: issue all gathers (independent, no branches between).
        unsigned p[BATCH];
        unsigned v[BATCH];
        #pragma unroll
        for (int k = 0; k < BATCH; ++k) {
            if (k < cnt) {
                p[k] = sh[j0 + k];
                v[k] = g_ATq[(size_t)(p[k] & 0x3FFFFFFFu) + tid];
            }
        }

        // Pass B: scalar consume (loads already in flight).
        #pragma unroll
        for (int k = 0; k < BATCH; ++k) {
            if (k < cnt) {
                if (p[k] & 0x80000000u) {        // row change, uniform
                    sum += (float)(abs(a0) + abs(a1) + abs(a2) + abs(a3));
                    a0 = 0; a1 = 0; a2 = 0; a3 = 0;
                }
                const unsigned u = v[k];
                const int smul = 1 - 2 * (int)((p[k] >> 30) & 1u);
                a0 += smul * (int)(signed char)(u);
                a1 += smul * (int)(signed char)(u >> 8);
                a2 += smul * (int)(signed char)(u >> 16);
                a3 += smul * (int)(signed char)(u >> 24);
            }
        }
    }

    // Fallback (statistically never taken): the block's last row extends
    // beyond the staged window -> finish it straight from global memory.
    if (en == n && st < en && base + n < E) {
        const int row = __ldg(&cyrows[base + n - 1]);
        for (int e = base + n; e < E && __ldg(&cyrows[e]) == row; ++e) {
            const int idx = __ldg(&cyinds[e]);
            const unsigned u = g_ATq[(size_t)idx * B_UINT + tid];
            const int smul =
                1 - 2 * (int)(__float_as_uint(__ldg(&cysigns[e])) >> 31);
            a0 += smul * (int)(signed char)(u);
            a1 += smul * (int)(signed char)(u >> 8);
            a2 += smul * (int)(signed char)(u >> 16);
            a3 += smul * (int)(signed char)(u >> 24);
        }
    }

    // Final row flush.
    sum += (float)(abs(a0) + abs(a1) + abs(a2) + abs(a3));

    // Block reduction (2 warps)
    #pragma unroll
    for (int off = 16; off > 0; off >>= 1)
        sum += __shfl_down_sync(0xFFFFFFFFu, sum, off);
    const int lane = tid & 31, wid = tid >> 5;
    if (lane == 0) warp_sums[wid] = sum;
    __syncthreads();
    if (tid == 0) {
        const float w = warp_sums[0] + warp_sums[1];
        if (w != 0.0f) atomicAdd(&g_accum, (double)w);
        __threadfence();
        const unsigned ticket = atomicAdd(&g_done, 1u);
        if (ticket == (unsigned)(gridDim.x - 1)) {
            __threadfence();
            const double total = *((volatile double*)&g_accum);
            // Undo quantization scale (pi/127) and take the mean.
            out[0] = (float)(total * (3.14159265358979323846 / 127.0)
                                   * (1.0 / ((double)N_CYC * (double)B_DIM)));
            // Self-clean so the next launch/replay starts from zero even
            // without phase1's reset.
            g_accum = 0.0;
            g_done = 0u;
            __threadfence();
        }
    }
}

extern "C" void kernel_launch(void* const* d_in, const int* in_sizes, int n_in,
                              void* d_out, int out_size) {
    const float* c       = (const float*)d_in[0];
    const float* s       = (const float*)d_in[1];
    const float* cysigns = (const float*)d_in[2];
    const int*   cyinds  = (const int*)d_in[3];
    const int*   cyrows  = (const int*)d_in[4];
    float* out = (float*)d_out;
    const int E = in_sizes[4];

    dim3 t1(16, 16);
    dim3 g1((NB_DIM + 63) / 64, B_DIM / 64);
    phase1_atan2_transpose<<<g1, t1>>>(c, s);

    const int g2 = (E + P2_BASE - 1) / P2_BASE;
    phase2_cycle_sum<<<g2, P2_THREADS>>>(cysigns, cyinds, cyrows, out, E);
}